// round 1
// baseline (speedup 1.0000x reference)
#include <cuda_runtime.h>

// ---------------- problem constants ----------------
#define Bn   8
#define Sn   512
#define Ln   6
#define Dn   512
#define Hn   8
#define HDn  64
#define HIDn 2048
#define Cn   256
#define INDIM 257
#define Mn   (Bn * Sn)          // 4096 rows

#define OUT_LOGITS_PER_B 1020   // 2 * 510
#define OUT_FEAS_OFF     (Bn * OUT_LOGITS_PER_B)   // 8160

// ---------------- scratch (device globals; no allocation) ----------------
__device__ float g_x  [Mn * Dn];            // residual stream
__device__ float g_q  [Mn * Dn];
__device__ float g_k  [Mn * Dn];
__device__ float g_v  [Mn * Dn];
__device__ float g_att[Mn * Dn];            // attention output (pre O-proj)
__device__ float g_sc [(size_t)Bn * Hn * Sn * Sn];   // 64 MB scores
__device__ float g_h  [Mn * HIDn];          // FFN hidden

// ============================================================
// 1) Build x = class_proj(concat(embed[idx], nd))  per row
// ============================================================
__global__ void build_x_kernel(const float* __restrict__ sol,
                               const float* __restrict__ cap,
                               const float* __restrict__ emb,
                               const float* __restrict__ srcW, const float* __restrict__ srcB,
                               const float* __restrict__ candW, const float* __restrict__ candB,
                               const float* __restrict__ depW, const float* __restrict__ depB)
{
    int row = blockIdx.x;            // 0..4095
    int b = row / Sn, s = row % Sn;
    __shared__ float xin[INDIM];
    int t = threadIdx.x;             // 256 threads

    int idx = (int)sol[(size_t)row * 4 + 0];
    xin[t] = emb[(size_t)idx * Cn + t];
    if (t == 0) {
        float rem = sol[(size_t)(b * Sn) * 4 + 3];
        float nd = (s == 0) ? 0.0f
                            : 2.0f * (sol[(size_t)row * 4 + 2] - rem) / cap[b];
        xin[Cn] = nd;
    }
    __syncthreads();

    const float* W; const float* bb;
    if (s == 0)           { W = srcW;  bb = srcB;  }
    else if (s == Sn - 1) { W = depW;  bb = depB;  }
    else                  { W = candW; bb = candB; }

    int c = t;                       // two columns per thread: c, c+256
    float acc0 = bb[c], acc1 = bb[c + 256];
    #pragma unroll 4
    for (int k = 0; k < INDIM; k++) {
        float xv = xin[k];
        acc0 += xv * W[k * Dn + c];
        acc1 += xv * W[k * Dn + c + 256];
    }
    g_x[(size_t)row * Dn + c]       = acc0;
    g_x[(size_t)row * Dn + c + 256] = acc1;
}

// ============================================================
// 2) Generic GEMM: C[M,N] = A[M,K] @ B[K,N] + bias (+ Res, +ReLU)
//    BM=BN=64, BK=16, 256 threads, 4x4 micro-tile, float4 smem reads
// ============================================================
template<bool RELU, bool RES>
__global__ __launch_bounds__(256) void gemm_kernel(
    const float* __restrict__ A, const float* __restrict__ Bw,
    const float* __restrict__ bias, const float* __restrict__ Res,
    float* __restrict__ C, int K, int N)
{
    const int t  = threadIdx.x;
    const int tx = t & 15, ty = t >> 4;
    const int m0 = blockIdx.y * 64, n0 = blockIdx.x * 64;

    __shared__ float As[16][68];   // [k][m], pad 4 keeps float4 alignment
    __shared__ float Bs[16][64];   // [k][n]

    const int am  = t >> 2;            // 0..63 (row of A tile)
    const int ak4 = (t & 3) * 4;       // k offset (float4)
    const int bk  = t >> 4;            // 0..15 (k row of B tile)
    const int bn4 = (t & 15) * 4;      // n offset (float4)

    float acc[4][4] = {};

    for (int k0 = 0; k0 < K; k0 += 16) {
        float4 a4 = *(const float4*)&A[(size_t)(m0 + am) * K + k0 + ak4];
        As[ak4 + 0][am] = a4.x; As[ak4 + 1][am] = a4.y;
        As[ak4 + 2][am] = a4.z; As[ak4 + 3][am] = a4.w;
        *(float4*)&Bs[bk][bn4] =
            *(const float4*)&Bw[(size_t)(k0 + bk) * N + n0 + bn4];
        __syncthreads();
        #pragma unroll
        for (int kk = 0; kk < 16; kk++) {
            float4 av = *(const float4*)&As[kk][ty * 4];
            float4 bv = *(const float4*)&Bs[kk][tx * 4];
            float a[4] = {av.x, av.y, av.z, av.w};
            float b[4] = {bv.x, bv.y, bv.z, bv.w};
            #pragma unroll
            for (int i = 0; i < 4; i++)
                #pragma unroll
                for (int j = 0; j < 4; j++)
                    acc[i][j] += a[i] * b[j];
        }
        __syncthreads();
    }

    float4 bi = *(const float4*)&bias[n0 + tx * 4];
    float bvv[4] = {bi.x, bi.y, bi.z, bi.w};
    #pragma unroll
    for (int i = 0; i < 4; i++) {
        int m = m0 + ty * 4 + i;
        float4 o;
        float v0 = acc[i][0] + bvv[0];
        float v1 = acc[i][1] + bvv[1];
        float v2 = acc[i][2] + bvv[2];
        float v3 = acc[i][3] + bvv[3];
        if (RELU) { v0 = fmaxf(v0, 0.f); v1 = fmaxf(v1, 0.f);
                    v2 = fmaxf(v2, 0.f); v3 = fmaxf(v3, 0.f); }
        if (RES) {
            float4 r = *(const float4*)&Res[(size_t)m * N + n0 + tx * 4];
            v0 += r.x; v1 += r.y; v2 += r.z; v3 += r.w;
        }
        o.x = v0; o.y = v1; o.z = v2; o.w = v3;
        *(float4*)&C[(size_t)m * N + n0 + tx * 4] = o;
    }
}

// ============================================================
// 3) scores[bh, q, k] = 0.125 * sum_e Q[b,q,h,e] * K[b,k,h,e]
//    (constant +s*log(n) bias is softmax-invariant -> skipped)
// ============================================================
__global__ __launch_bounds__(256) void scores_kernel()
{
    int bh = blockIdx.z; int b = bh >> 3, h = bh & 7;
    int q0 = blockIdx.y * 64, k0 = blockIdx.x * 64;
    __shared__ float Qs[64][68];   // [e][q]
    __shared__ float Ks[64][68];   // [e][k]
    int t = threadIdx.x, tx = t & 15, ty = t >> 4;

    int r  = t >> 2;              // tile row 0..63
    int e0 = (t & 3) * 4;
    const float* Qp = g_q + ((size_t)(b * Sn + q0 + r)) * Dn + h * HDn;
    const float* Kp = g_k + ((size_t)(b * Sn + k0 + r)) * Dn + h * HDn;
    #pragma unroll
    for (int ee = 0; ee < 64; ee += 16) {
        float4 q4 = *(const float4*)&Qp[e0 + ee];
        Qs[e0 + ee + 0][r] = q4.x; Qs[e0 + ee + 1][r] = q4.y;
        Qs[e0 + ee + 2][r] = q4.z; Qs[e0 + ee + 3][r] = q4.w;
        float4 k4 = *(const float4*)&Kp[e0 + ee];
        Ks[e0 + ee + 0][r] = k4.x; Ks[e0 + ee + 1][r] = k4.y;
        Ks[e0 + ee + 2][r] = k4.z; Ks[e0 + ee + 3][r] = k4.w;
    }
    __syncthreads();

    float acc[4][4] = {};
    #pragma unroll
    for (int e = 0; e < 64; e++) {
        float4 av = *(const float4*)&Qs[e][ty * 4];
        float4 bv = *(const float4*)&Ks[e][tx * 4];
        float a[4] = {av.x, av.y, av.z, av.w};
        float b2[4] = {bv.x, bv.y, bv.z, bv.w};
        #pragma unroll
        for (int i = 0; i < 4; i++)
            #pragma unroll
            for (int j = 0; j < 4; j++)
                acc[i][j] += a[i] * b2[j];
    }
    float* Sp = g_sc + (size_t)bh * Sn * Sn;
    #pragma unroll
    for (int i = 0; i < 4; i++) {
        float4 o = make_float4(acc[i][0] * 0.125f, acc[i][1] * 0.125f,
                               acc[i][2] * 0.125f, acc[i][3] * 0.125f);
        *(float4*)&Sp[(size_t)(q0 + ty * 4 + i) * Sn + k0 + tx * 4] = o;
    }
}

// ============================================================
// 4) row softmax over the 512-wide score rows
// ============================================================
__global__ void softmax_kernel()
{
    size_t row = blockIdx.x;
    float* p = g_sc + row * Sn;
    int t = threadIdx.x;                       // 256 threads
    float2 v = ((float2*)p)[t];
    __shared__ float red[256];
    red[t] = fmaxf(v.x, v.y);
    __syncthreads();
    for (int o = 128; o > 0; o >>= 1) {
        if (t < o) red[t] = fmaxf(red[t], red[t + o]);
        __syncthreads();
    }
    float mx = red[0];
    __syncthreads();
    v.x = __expf(v.x - mx); v.y = __expf(v.y - mx);
    red[t] = v.x + v.y;
    __syncthreads();
    for (int o = 128; o > 0; o >>= 1) {
        if (t < o) red[t] += red[t + o];
        __syncthreads();
    }
    float inv = 1.0f / red[0];
    v.x *= inv; v.y *= inv;
    ((float2*)p)[t] = v;
}

// ============================================================
// 5) att[b,q,h,:] = softmax_scores[bh] @ V[b,:,h,:]
// ============================================================
__global__ __launch_bounds__(256) void av_kernel()
{
    int bh = blockIdx.y; int b = bh >> 3, h = bh & 7;
    int q0 = blockIdx.x * 64;
    const float* Wsc = g_sc + (size_t)bh * Sn * Sn;
    const float* Vp  = g_v + ((size_t)(b * Sn)) * Dn + h * HDn;

    __shared__ float Ws[32][68];   // [k][q]
    __shared__ float Vs[32][64];   // [k][e]
    int t = threadIdx.x, tx = t & 15, ty = t >> 4;

    int wq  = t >> 2;              // 0..63
    int wk4 = (t & 3) * 4;
    int vk  = t >> 4;              // 0..15
    int ve4 = (t & 15) * 4;

    float acc[4][4] = {};
    for (int k0 = 0; k0 < Sn; k0 += 32) {
        #pragma unroll
        for (int half = 0; half < 2; half++) {
            float4 w4 = *(const float4*)&Wsc[(size_t)(q0 + wq) * Sn + k0 + wk4 + half * 16];
            Ws[wk4 + half * 16 + 0][wq] = w4.x;
            Ws[wk4 + half * 16 + 1][wq] = w4.y;
            Ws[wk4 + half * 16 + 2][wq] = w4.z;
            Ws[wk4 + half * 16 + 3][wq] = w4.w;
            *(float4*)&Vs[vk + half * 16][ve4] =
                *(const float4*)&Vp[(size_t)(k0 + vk + half * 16) * Dn + ve4];
        }
        __syncthreads();
        #pragma unroll
        for (int kk = 0; kk < 32; kk++) {
            float4 av = *(const float4*)&Ws[kk][ty * 4];
            float4 bv = *(const float4*)&Vs[kk][tx * 4];
            float a[4] = {av.x, av.y, av.z, av.w};
            float b2[4] = {bv.x, bv.y, bv.z, bv.w};
            #pragma unroll
            for (int i = 0; i < 4; i++)
                #pragma unroll
                for (int j = 0; j < 4; j++)
                    acc[i][j] += a[i] * b2[j];
        }
        __syncthreads();
    }
    #pragma unroll
    for (int i = 0; i < 4; i++) {
        float4 o = make_float4(acc[i][0], acc[i][1], acc[i][2], acc[i][3]);
        *(float4*)&g_att[(size_t)(b * Sn + q0 + ty * 4 + i) * Dn + h * HDn + tx * 4] = o;
    }
}

// ============================================================
// 6) feasibility head: feas[b,s-1] = x[b,s] . feas_W + feas_b
// ============================================================
__global__ void feas_kernel(const float* __restrict__ fW,
                            const float* __restrict__ fB,
                            float* __restrict__ out)
{
    int s = blockIdx.x + 1;        // 1..510
    int b = blockIdx.y;
    const float* xr = g_x + (size_t)(b * Sn + s) * Dn;
    int t = threadIdx.x;           // 128
    float acc = 0.f;
    #pragma unroll 4
    for (int k = t; k < Dn; k += 128) acc += xr[k] * fW[k];
    __shared__ float red[128];
    red[t] = acc; __syncthreads();
    for (int o = 64; o > 0; o >>= 1) {
        if (t < o) red[t] += red[t + o];
        __syncthreads();
    }
    if (t == 0) out[OUT_FEAS_OFF + b * 510 + (s - 1)] = red[0] + fB[0];
}

// ============================================================
// 7) pointer logits: out[b, s-1] / out[b, 510 + s-1]
// ============================================================
__global__ void logits_kernel(const float* __restrict__ pW,
                              const float* __restrict__ pB,
                              float* __restrict__ out)
{
    int s = blockIdx.x + 1;        // 1..510
    int b = blockIdx.y;
    const float* xr = g_x + (size_t)(b * Sn + s) * Dn;
    int t = threadIdx.x;           // 128
    float a0 = 0.f, a1 = 0.f;
    #pragma unroll 4
    for (int k = t; k < Dn; k += 128) {
        float xv = xr[k];
        a0 += xv * pW[k * 2 + 0];
        a1 += xv * pW[k * 2 + 1];
    }
    __shared__ float r0[128], r1[128];
    r0[t] = a0; r1[t] = a1; __syncthreads();
    for (int o = 64; o > 0; o >>= 1) {
        if (t < o) { r0[t] += r0[t + o]; r1[t] += r1[t + o]; }
        __syncthreads();
    }
    if (t == 0) {
        out[b * OUT_LOGITS_PER_B + (s - 1)]       = r0[0] + pB[0];
        out[b * OUT_LOGITS_PER_B + 510 + (s - 1)] = r1[0] + pB[1];
    }
}

// ============================================================
// host orchestration
// ============================================================
extern "C" void kernel_launch(void* const* d_in, const int* in_sizes, int n_in,
                              void* d_out, int out_size)
{
    const float* sol   = (const float*)d_in[0];
    const float* cap   = (const float*)d_in[1];
    const float* emb   = (const float*)d_in[2];
    const float* srcW  = (const float*)d_in[3];
    const float* srcB  = (const float*)d_in[4];
    const float* candW = (const float*)d_in[5];
    const float* candB = (const float*)d_in[6];
    const float* depW  = (const float*)d_in[7];
    const float* depB  = (const float*)d_in[8];
    const float* feasW = (const float*)d_in[9];
    const float* feasB = (const float*)d_in[10];
    const float* Wq    = (const float*)d_in[11];
    const float* bq    = (const float*)d_in[12];
    const float* Wk    = (const float*)d_in[13];
    const float* bk    = (const float*)d_in[14];
    const float* Wv    = (const float*)d_in[15];
    const float* bv    = (const float*)d_in[16];
    const float* Wo    = (const float*)d_in[17];
    const float* bo    = (const float*)d_in[18];
    // d_in[19] = s_scale : softmax-shift-invariant, unused
    const float* W1    = (const float*)d_in[20];
    const float* b1    = (const float*)d_in[21];
    const float* W2    = (const float*)d_in[22];
    const float* b2    = (const float*)d_in[23];
    const float* ptrW  = (const float*)d_in[24];
    const float* ptrB  = (const float*)d_in[25];
    float* out = (float*)d_out;
    (void)in_sizes; (void)n_in; (void)out_size;

    float *px, *pq, *pk, *pv, *patt, *ph;
    cudaGetSymbolAddress((void**)&px,   g_x);
    cudaGetSymbolAddress((void**)&pq,   g_q);
    cudaGetSymbolAddress((void**)&pk,   g_k);
    cudaGetSymbolAddress((void**)&pv,   g_v);
    cudaGetSymbolAddress((void**)&patt, g_att);
    cudaGetSymbolAddress((void**)&ph,   g_h);

    const dim3 gProj(Dn / 64, Mn / 64);     // (8, 64)  N=512
    const dim3 gFF1(HIDn / 64, Mn / 64);    // (32, 64) N=2048
    const dim3 gScores(8, 8, 64);
    const dim3 gAv(8, 64);

    build_x_kernel<<<Mn, 256>>>(sol, cap, emb, srcW, srcB, candW, candB, depW, depB);

    for (int i = 0; i < Ln; i++) {
        const float* wq = Wq + (size_t)i * Dn * Dn;
        const float* wk = Wk + (size_t)i * Dn * Dn;
        const float* wv = Wv + (size_t)i * Dn * Dn;
        const float* wo = Wo + (size_t)i * Dn * Dn;
        const float* w1 = W1 + (size_t)i * Dn * HIDn;
        const float* w2 = W2 + (size_t)i * HIDn * Dn;

        // ---- MHA ----
        gemm_kernel<false, false><<<gProj, 256>>>(px, wq, bq + i * Dn, nullptr, pq, Dn, Dn);
        gemm_kernel<false, false><<<gProj, 256>>>(px, wk, bk + i * Dn, nullptr, pk, Dn, Dn);
        gemm_kernel<false, false><<<gProj, 256>>>(px, wv, bv + i * Dn, nullptr, pv, Dn, Dn);
        scores_kernel<<<gScores, 256>>>();
        softmax_kernel<<<Bn * Hn * Sn, 256>>>();
        av_kernel<<<gAv, 256>>>();
        gemm_kernel<false, true><<<gProj, 256>>>(patt, wo, bo + i * Dn, px, px, Dn, Dn);

        // feasibility head reads x right after layer-0 attention residual
        if (i == 0)
            feas_kernel<<<dim3(510, Bn), 128>>>(feasW, feasB, out);

        // ---- FFN ----
        gemm_kernel<true,  false><<<gFF1, 256>>>(px, w1, b1 + i * HIDn, nullptr, ph, Dn, HIDn);
        gemm_kernel<false, true ><<<gProj, 256>>>(ph, w2, b2 + i * Dn, px, px, HIDn, Dn);
    }

    logits_kernel<<<dim3(510, Bn), 128>>>(ptrW, ptrB, out);
}